// round 6
// baseline (speedup 1.0000x reference)
#include <cuda_runtime.h>
#include <cuda_bf16.h>
#include <math.h>
#include <stdint.h>

// ---------------------------------------------------------------------------
// CellMatesTransformer forward. mma.sync bf16 split GEMMs (pipelined).
// NL=8, B=4, L=512, D=512, H=16, KH=32, FF=2048, NCT=6, ND=14
// ---------------------------------------------------------------------------

#define NLAYERS 8
#define BSZ     4
#define SEQ     512
#define DIM     512
#define NHEAD   16
#define KHD     32
#define FFD     2048
#define NDB     14
#define NROWS   (BSZ*SEQ)      // 2048
#define QKVN    (3*DIM)        // 1536

#define ATT_SCALE 0.17677669529663687f   // 1/sqrt(32)

// ------------------------- scratch (device globals) ------------------------
__device__ float g_h  [NROWS*DIM];
__device__ float g_h2 [NROWS*DIM];
__device__ float g_qkv[NROWS*QKVN];
__device__ float g_o  [NROWS*DIM];
__device__ unsigned char g_didx[BSZ*SEQ*SEQ];
__device__ float g_ekr [BSZ*SEQ*SEQ];

// split activations
__device__ __nv_bfloat16 g_xhi[NROWS*DIM];
__device__ __nv_bfloat16 g_xlo[NROWS*DIM];
__device__ __nv_bfloat16 g_fhi[NROWS*FFD];
__device__ __nv_bfloat16 g_flo[NROWS*FFD];

// split weights (pre-transposed, K-major)
__device__ __nv_bfloat16 g_wqkv_hi[NLAYERS*QKVN*DIM];
__device__ __nv_bfloat16 g_wqkv_lo[NLAYERS*QKVN*DIM];
__device__ __nv_bfloat16 g_wo_hi[NLAYERS*DIM*DIM];
__device__ __nv_bfloat16 g_wo_lo[NLAYERS*DIM*DIM];
__device__ __nv_bfloat16 g_w1_hi[NLAYERS*FFD*DIM];
__device__ __nv_bfloat16 g_w1_lo[NLAYERS*FFD*DIM];
__device__ __nv_bfloat16 g_w2_hi[NLAYERS*DIM*FFD];
__device__ __nv_bfloat16 g_w2_lo[NLAYERS*DIM*FFD];
__device__ float g_bqkv[NLAYERS*QKVN];

// ------------------------- PTX helpers --------------------------------------

__device__ __forceinline__ uint32_t smem_u32(const void* p) {
    uint32_t a;
    asm("{ .reg .u64 t; cvta.to.shared.u64 t, %1; cvt.u32.u64 %0, t; }" : "=r"(a) : "l"(p));
    return a;
}
#define SW128(off) ((off) ^ (((off) >> 3) & 0x70))

#define CP_ASYNC16(sm, gp) \
    asm volatile("cp.async.cg.shared.global [%0], [%1], 16;" :: "r"(sm), "l"(gp) : "memory")
#define CP_COMMIT() asm volatile("cp.async.commit_group;" ::: "memory")

#define LDSM4(r0, r1, r2, r3, addr) \
    asm volatile("ldmatrix.sync.aligned.m8n8.x4.shared.b16 {%0,%1,%2,%3}, [%4];" \
        : "=r"(r0), "=r"(r1), "=r"(r2), "=r"(r3) : "r"(addr))

#define MMA16816(c, a, b0, b1) \
    asm volatile("mma.sync.aligned.m16n8k16.row.col.f32.bf16.bf16.f32 " \
        "{%0,%1,%2,%3}, {%4,%5,%6,%7}, {%8,%9}, {%0,%1,%2,%3};" \
        : "+f"((c)[0]), "+f"((c)[1]), "+f"((c)[2]), "+f"((c)[3]) \
        : "r"((a)[0]), "r"((a)[1]), "r"((a)[2]), "r"((a)[3]), "r"(b0), "r"(b1))

__device__ __forceinline__ void split_bf16(float v, __nv_bfloat16& h, __nv_bfloat16& l) {
    h = __float2bfloat16(v);
    l = __float2bfloat16(v - __bfloat162float(h));
}

// ------------------------- precompute kernels ------------------------------

__global__ __launch_bounds__(256) void init_h_kernel(
    const int* __restrict__ cell_types, const float* __restrict__ cell_emb)
{
    int i = blockIdx.x * 256 + threadIdx.x;
    int row = i >> 9, d = i & 511;
    float v = cell_emb[cell_types[row] * DIM + d];
    g_h[i] = v;
    split_bf16(v, g_xhi[i], g_xlo[i]);
}

__global__ __launch_bounds__(256) void prep_kernel(
    const float* __restrict__ dist, const float* __restrict__ Kkr)
{
    __shared__ float ksum[NDB];
    if (threadIdx.x < NDB) {
        float s = 0.f;
        #pragma unroll
        for (int kk = 0; kk < KHD; kk++) s += Kkr[threadIdx.x * KHD + kk];
        ksum[threadIdx.x] = s;
    }
    __syncthreads();
    int i = blockIdx.x * 256 + threadIdx.x;
    float dv = dist[i];
    int idx = 0;
    #pragma unroll
    for (int j = 1; j <= NDB; j++) idx += (dv > 10.0f * (float)j);
    if (idx > NDB - 1) idx = NDB - 1;
    g_didx[i] = (unsigned char)idx;
    g_ekr[i]  = ksum[idx];
}

// weight transpose + split, batched over layers (grid.z)
__global__ __launch_bounds__(256) void cvt_w_kernel(
    const float* __restrict__ W, __nv_bfloat16* __restrict__ hi,
    __nv_bfloat16* __restrict__ lo, int K, int N,
    size_t srcStride, size_t dstStride)
{
    __shared__ float t[32][33];
    const float* Ws = W + (size_t)blockIdx.z * srcStride;
    __nv_bfloat16* hid = hi + (size_t)blockIdx.z * dstStride;
    __nv_bfloat16* lod = lo + (size_t)blockIdx.z * dstStride;
    int k0 = blockIdx.y * 32, n0 = blockIdx.x * 32;
    int tx = threadIdx.x & 31, ty = threadIdx.x >> 5;
    #pragma unroll
    for (int r = 0; r < 4; r++)
        t[ty + 8 * r][tx] = Ws[(size_t)(k0 + ty + 8 * r) * N + n0 + tx];
    __syncthreads();
    #pragma unroll
    for (int r = 0; r < 4; r++) {
        int n = n0 + ty + 8 * r, k = k0 + tx;
        float v = t[tx][ty + 8 * r];
        __nv_bfloat16 h, l;
        split_bf16(v, h, l);
        hid[(size_t)n * K + k] = h;
        lod[(size_t)n * K + k] = l;
    }
}

__global__ __launch_bounds__(256) void pack_bqkv_kernel(
    const float* __restrict__ bq, const float* __restrict__ bk,
    const float* __restrict__ bv)
{
    int i = blockIdx.x * 256 + threadIdx.x;
    int li = i / QKVN, j = i % QKVN;
    float v;
    if (j < DIM)            v = bq[li * DIM + j];
    else if (j < 2 * DIM)   v = bk[li * DIM + j - DIM];
    else                    v = bv[li * DIM + j - 2 * DIM];
    g_bqkv[i] = v;
}

// ------------------------- mma.sync GEMM ------------------------------------
// CTA tile 128 x 64, 256 thr (4x2 warps, 32x32 warp tiles).
// 3-stage cp.async pipeline, K chunks of 64, fragment double-buffering,
// term-major MMA order.  mode 0: fp32 out.  mode 2: GELU + split bf16 out.

#define GSM_BUF   49152
#define GSM_TOTAL (3*GSM_BUF)

__device__ __forceinline__ void load_chunk(
    uint32_t base, int tid,
    const __nv_bfloat16* Ahi, const __nv_bfloat16* Alo,
    const __nv_bfloat16* Bhi, const __nv_bfloat16* Blo,
    int rowBase, int colBase, int K, int k0)
{
    #pragma unroll
    for (int t = 0; t < 4; t++) {
        int idx = tid + (t << 8);
        int r = idx >> 3, seg = idx & 7;
        uint32_t so = SW128((uint32_t)(r * 128 + seg * 16));
        size_t goff = (size_t)(rowBase + r) * K + k0 + seg * 8;
        CP_ASYNC16(base + so,         Ahi + goff);
        CP_ASYNC16(base + 16384 + so, Alo + goff);
    }
    #pragma unroll
    for (int t = 0; t < 2; t++) {
        int idx = tid + (t << 8);
        int r = idx >> 3, seg = idx & 7;
        uint32_t so = SW128((uint32_t)(r * 128 + seg * 16));
        size_t goff = (size_t)(colBase + r) * K + k0 + seg * 8;
        CP_ASYNC16(base + 32768 + so, Bhi + goff);
        CP_ASYNC16(base + 40960 + so, Blo + goff);
    }
}

struct Frags {
    uint32_t ah[2][4], al[2][4], bh[2][4], bl[2][4];
};

__device__ __forceinline__ void load_frags(
    uint32_t base, int wr, int wc, int rA, int hs, int ks, Frags& f)
{
    int segoff = (ks * 2 + hs) * 16;
    #pragma unroll
    for (int mt = 0; mt < 2; mt++) {
        int row = wr * 32 + mt * 16 + rA;
        uint32_t off = SW128((uint32_t)(row * 128 + segoff));
        LDSM4(f.ah[mt][0], f.ah[mt][1], f.ah[mt][2], f.ah[mt][3], base + off);
        LDSM4(f.al[mt][0], f.al[mt][1], f.al[mt][2], f.al[mt][3], base + 16384 + off);
    }
    #pragma unroll
    for (int g = 0; g < 2; g++) {
        int row = wc * 32 + g * 16 + rA;
        uint32_t off = SW128((uint32_t)(row * 128 + segoff));
        LDSM4(f.bh[g][0], f.bh[g][1], f.bh[g][2], f.bh[g][3], base + 32768 + off);
        LDSM4(f.bl[g][0], f.bl[g][1], f.bl[g][2], f.bl[g][3], base + 40960 + off);
    }
}

__device__ __forceinline__ void mma_frags(float acc[2][4][4], const Frags& f)
{
    // term-major: independent MMAs between same-acc RAW pairs
    #pragma unroll
    for (int mt = 0; mt < 2; mt++)
        #pragma unroll
        for (int nt = 0; nt < 4; nt++) {
            int g = nt >> 1, s = nt & 1;
            MMA16816(acc[mt][nt], f.ah[mt], f.bh[g][s], f.bh[g][s + 2]);
        }
    #pragma unroll
    for (int mt = 0; mt < 2; mt++)
        #pragma unroll
        for (int nt = 0; nt < 4; nt++) {
            int g = nt >> 1, s = nt & 1;
            MMA16816(acc[mt][nt], f.ah[mt], f.bl[g][s], f.bl[g][s + 2]);
        }
    #pragma unroll
    for (int mt = 0; mt < 2; mt++)
        #pragma unroll
        for (int nt = 0; nt < 4; nt++) {
            int g = nt >> 1, s = nt & 1;
            MMA16816(acc[mt][nt], f.al[mt], f.bh[g][s], f.bh[g][s + 2]);
        }
}

__global__ __launch_bounds__(256) void gemm_mma_kernel(
    const __nv_bfloat16* __restrict__ Ahi, const __nv_bfloat16* __restrict__ Alo,
    const __nv_bfloat16* __restrict__ Bhi, const __nv_bfloat16* __restrict__ Blo,
    const float* __restrict__ bias, float* __restrict__ C,
    __nv_bfloat16* __restrict__ Chi, __nv_bfloat16* __restrict__ Clo,
    int N, int K, int mode)
{
    extern __shared__ char smem[];
    uint32_t sb = smem_u32(smem);
    int tid = threadIdx.x, wid = tid >> 5, lane = tid & 31;
    int wr = wid >> 1, wc = wid & 1;
    int rowBase = blockIdx.y * 128, colBase = blockIdx.x * 64;
    int S = K >> 6;
    int rA = lane & 15, hs = lane >> 4;

    float acc[2][4][4];
    #pragma unroll
    for (int mt = 0; mt < 2; mt++)
        #pragma unroll
        for (int nt = 0; nt < 4; nt++)
            #pragma unroll
            for (int e = 0; e < 4; e++) acc[mt][nt][e] = 0.f;

    load_chunk(sb,           tid, Ahi, Alo, Bhi, Blo, rowBase, colBase, K, 0);
    CP_COMMIT();
    load_chunk(sb + GSM_BUF, tid, Ahi, Alo, Bhi, Blo, rowBase, colBase, K, (1 < S ? 1 : 0) << 6);
    CP_COMMIT();

    int bufIdx[3] = {0, GSM_BUF, 2 * GSM_BUF};

    for (int i = 0; i < S; i++) {
        asm volatile("cp.async.wait_group 1;" ::: "memory");
        __syncthreads();

        // issue chunk i+2 (clamped redundant tail load keeps group count uniform)
        int nx = (i + 2 < S) ? i + 2 : S - 1;
        load_chunk(sb + bufIdx[(i + 2) % 3], tid, Ahi, Alo, Bhi, Blo,
                   rowBase, colBase, K, nx << 6);
        CP_COMMIT();

        uint32_t base = sb + bufIdx[i % 3];
        Frags f0, f1;
        load_frags(base, wr, wc, rA, hs, 0, f0);
        #pragma unroll
        for (int ks = 0; ks < 4; ks++) {
            if (ks & 1) {
                if (ks < 3) load_frags(base, wr, wc, rA, hs, ks + 1, f0);
                mma_frags(acc, f1);
            } else {
                if (ks < 3) load_frags(base, wr, wc, rA, hs, ks + 1, f1);
                mma_frags(acc, f0);
            }
        }
    }

    int tg = lane >> 2, tq = lane & 3;
    #pragma unroll
    for (int mt = 0; mt < 2; mt++) {
        #pragma unroll
        for (int nt = 0; nt < 4; nt++) {
            int c0 = colBase + wc * 32 + nt * 8 + tq * 2;
            float b0 = bias[c0], b1 = bias[c0 + 1];
            int r0 = rowBase + wr * 32 + mt * 16 + tg;
            float v00 = acc[mt][nt][0] + b0, v01 = acc[mt][nt][1] + b1;
            float v10 = acc[mt][nt][2] + b0, v11 = acc[mt][nt][3] + b1;
            if (mode == 2) {
                v00 = 0.5f * v00 * (1.0f + erff(v00 * 0.70710678118654752f));
                v01 = 0.5f * v01 * (1.0f + erff(v01 * 0.70710678118654752f));
                v10 = 0.5f * v10 * (1.0f + erff(v10 * 0.70710678118654752f));
                v11 = 0.5f * v11 * (1.0f + erff(v11 * 0.70710678118654752f));
                __nv_bfloat162 h0, l0, h1, l1;
                split_bf16(v00, h0.x, l0.x); split_bf16(v01, h0.y, l0.y);
                split_bf16(v10, h1.x, l1.x); split_bf16(v11, h1.y, l1.y);
                *(__nv_bfloat162*)&Chi[(size_t)r0 * N + c0]       = h0;
                *(__nv_bfloat162*)&Clo[(size_t)r0 * N + c0]       = l0;
                *(__nv_bfloat162*)&Chi[(size_t)(r0 + 8) * N + c0] = h1;
                *(__nv_bfloat162*)&Clo[(size_t)(r0 + 8) * N + c0] = l1;
            } else {
                *(float2*)&C[(size_t)r0 * N + c0]       = make_float2(v00, v01);
                *(float2*)&C[(size_t)(r0 + 8) * N + c0] = make_float2(v10, v11);
            }
        }
    }
}

// ------------------------- attention ----------------------------------------

#define ATT_SMEM_FLOATS (32*512 + 512*32 + 14*512 + 8*512 + 448*3 + 8*16)

__global__ __launch_bounds__(256) void attn_kernel(
    const float* __restrict__ Kqk, const float* __restrict__ Kqr,
    const float* __restrict__ Vqk, const float* __restrict__ Vqr,
    const float* __restrict__ Vkr)
{
    extern __shared__ float sm[];
    float* Kt    = sm;
    float* Vs    = Kt + 32 * 512;
    float* kEt   = Vs + 512 * 32;
    float* ps    = kEt + 14 * 512;
    float* tKqkT = ps + 8 * 512;
    float* tKqr  = tKqkT + 448;
    float* tVs   = tKqr + 448;
    float* wb    = tVs + 448;

    int bh = blockIdx.x;
    int b = bh >> 4, h = bh & 15;
    int tid = threadIdx.x, lane = tid & 31, warp = tid >> 5;

    const float* qb = g_qkv + ((size_t)b * SEQ) * QKVN + h * KHD;
    const float* kb = qb + DIM;
    const float* vb = qb + 2 * DIM;

    for (int i = tid; i < NDB * KHD; i += 256) {
        int d = i / KHD, kk = i % KHD;
        tKqkT[kk * NDB + d] = Kqk[i];
        tKqr[i] = Kqr[i];
        tVs[i]  = Vqk[i] + Vqr[i] + Vkr[i];
    }
    for (int i = tid; i < SEQ * 8; i += 256) {
        int x = i >> 3, g = (i & 7) << 2;
        float4 k4 = *(const float4*)&kb[(size_t)x * QKVN + g];
        Kt[(g + 0) * SEQ + x] = k4.x; Kt[(g + 1) * SEQ + x] = k4.y;
        Kt[(g + 2) * SEQ + x] = k4.z; Kt[(g + 3) * SEQ + x] = k4.w;
        float4 v4 = *(const float4*)&vb[(size_t)x * QKVN + g];
        *(float4*)&Vs[x * KHD + g] = v4;
    }
    __syncthreads();

    for (int i = tid; i < NDB * SEQ; i += 256) {
        int d = i >> 9, x = i & 511;
        float s = 0.f;
        #pragma unroll
        for (int kk = 0; kk < KHD; kk++)
            s = fmaf(Kt[kk * SEQ + x], tKqr[d * KHD + kk], s);
        kEt[i] = s;
    }
    __syncthreads();

    int l0 = blockIdx.y * 64 + warp * 8;
    for (int r = 0; r < 8; r++) {
        int l = l0 + r;
        float qreg = qb[(size_t)l * QKVN + lane];
        float e[16];
        #pragma unroll
        for (int j = 0; j < 16; j++) e[j] = 0.f;
        float qE = 0.f;
        #pragma unroll
        for (int kk = 0; kk < KHD; kk++) {
            float qk = __shfl_sync(0xffffffffu, qreg, kk);
            #pragma unroll
            for (int j = 0; j < 16; j++)
                e[j] = fmaf(qk, Kt[kk * SEQ + lane + j * 32], e[j]);
            if (lane < NDB) qE = fmaf(qk, tKqkT[kk * NDB + lane], qE);
        }

        const unsigned char* drow = &g_didx[((size_t)b * SEQ + l) * SEQ];
        const float*         erow = &g_ekr [((size_t)b * SEQ + l) * SEQ];
        int dly[16];
        float m = -1e30f;
        #pragma unroll
        for (int j = 0; j < 16; j++) {
            int x = lane + j * 32;
            int d = drow[x];
            dly[j] = d;
            float biasv = __shfl_sync(0xffffffffu, qE, d) + kEt[d * SEQ + x] + erow[x];
            e[j] = (e[j] + biasv) * ATT_SCALE;
            m = fmaxf(m, e[j]);
        }
        #pragma unroll
        for (int off = 16; off; off >>= 1)
            m = fmaxf(m, __shfl_xor_sync(0xffffffffu, m, off));

        if (lane < 16) wb[warp * 16 + lane] = 0.f;
        __syncwarp();

        float sum = 0.f;
        float pj[16];
        #pragma unroll
        for (int j = 0; j < 16; j++) {
            float p = expf(e[j] - m);
            pj[j] = p;
            sum += p;
            ps[warp * SEQ + lane + j * 32] = p;
        }
        #pragma unroll
        for (int off = 16; off; off >>= 1)
            sum += __shfl_xor_sync(0xffffffffu, sum, off);
        #pragma unroll
        for (int j = 0; j < 16; j++)
            atomicAdd(&wb[warp * 16 + dly[j]], pj[j]);
        __syncwarp();

        float acc = 0.f;
        const float* pw = &ps[warp * SEQ];
        for (int x = 0; x < SEQ; x += 4) {
            float4 p4 = *(const float4*)&pw[x];
            acc = fmaf(p4.x, Vs[(x + 0) * KHD + lane], acc);
            acc = fmaf(p4.y, Vs[(x + 1) * KHD + lane], acc);
            acc = fmaf(p4.z, Vs[(x + 2) * KHD + lane], acc);
            acc = fmaf(p4.w, Vs[(x + 3) * KHD + lane], acc);
        }
        #pragma unroll
        for (int d = 0; d < NDB; d++)
            acc = fmaf(wb[warp * 16 + d], tVs[d * KHD + lane], acc);

        float z = acc / sum;
        size_t oidx = ((size_t)b * SEQ + l) * DIM + h * KHD + lane;
        split_bf16(z, g_xhi[oidx], g_xlo[oidx]);
    }
}

// ------------------------- residual + layernorm (warp per row) --------------

__global__ __launch_bounds__(256) void add_ln_kernel(
    const float* __restrict__ x, const float* __restrict__ y,
    const float* __restrict__ g, const float* __restrict__ b,
    float* __restrict__ out)
{
    int warp = threadIdx.x >> 5, lane = threadIdx.x & 31;
    int row = blockIdx.x * 8 + warp;
    const float* xr = x + (size_t)row * DIM;
    const float* yr = y + (size_t)row * DIM;
    int c0 = lane * 16;

    float v[16];
    float s = 0.f, s2 = 0.f;
    #pragma unroll
    for (int j = 0; j < 16; j += 4) {
        float4 a4 = *(const float4*)&xr[c0 + j];
        float4 b4 = *(const float4*)&yr[c0 + j];
        v[j + 0] = a4.x + b4.x; v[j + 1] = a4.y + b4.y;
        v[j + 2] = a4.z + b4.z; v[j + 3] = a4.w + b4.w;
        #pragma unroll
        for (int q = 0; q < 4; q++) { s += v[j + q]; s2 += v[j + q] * v[j + q]; }
    }
    #pragma unroll
    for (int off = 16; off; off >>= 1) {
        s  += __shfl_xor_sync(0xffffffffu, s,  off);
        s2 += __shfl_xor_sync(0xffffffffu, s2, off);
    }
    float mu = s * (1.0f / 512.0f);
    float var = s2 * (1.0f / 512.0f) - mu * mu;
    float rs = rsqrtf(var + 1e-5f);

    size_t base = (size_t)row * DIM + c0;
    #pragma unroll
    for (int j = 0; j < 16; j++) {
        float o = (v[j] - mu) * rs * g[c0 + j] + b[c0 + j];
        out[base + j] = o;
        split_bf16(o, g_xhi[base + j], g_xlo[base + j]);
    }
}

// ------------------------- pooling + MLP head ------------------------------

__global__ __launch_bounds__(256) void head_kernel(
    const float* __restrict__ Wm1, const float* __restrict__ bm1,
    const float* __restrict__ Wm2, const float* __restrict__ bm2,
    float* __restrict__ out)
{
    __shared__ float pooled[DIM];
    __shared__ float hidden[DIM];
    __shared__ float red[256];
    int b = blockIdx.x, t = threadIdx.x;
    const float* hb = g_h + (size_t)b * SEQ * DIM;
    for (int d = t; d < DIM; d += 256) {
        float s = 0.f;
        for (int l = 0; l < SEQ; l++) s += hb[(size_t)l * DIM + d];
        pooled[d] = s;
    }
    __syncthreads();
    for (int m = t; m < DIM; m += 256) {
        float s = bm1[m];
        for (int kd = 0; kd < DIM; kd++)
            s = fmaf(pooled[kd], Wm1[(size_t)kd * DIM + m], s);
        hidden[m] = fmaxf(s, 0.f);
    }
    __syncthreads();
    red[t] = hidden[t] * Wm2[t] + hidden[t + 256] * Wm2[t + 256];
    __syncthreads();
    for (int s = 128; s; s >>= 1) { if (t < s) red[t] += red[t + s]; __syncthreads(); }
    if (t == 0) out[b] = red[0] + bm2[0];
}

// ------------------------- launcher ----------------------------------------

extern "C" void kernel_launch(void* const* d_in, const int* in_sizes, int n_in,
                              void* d_out, int out_size)
{
    (void)n_in; (void)out_size;

    const int*   cell_types = (const int*)  d_in[0];
    const float* dist       = (const float*)d_in[1];
    const float* cell_emb   = (const float*)d_in[2];
    const float* Kqk = (const float*)d_in[3];
    const float* Kqr = (const float*)d_in[4];
    const float* Kkr = (const float*)d_in[5];
    const float* Vqk = (const float*)d_in[6];
    const float* Vqr = (const float*)d_in[7];
    const float* Vkr = (const float*)d_in[8];

    const float *Wq, *bq, *Wk, *bk, *Wv, *bv, *Wo, *bo;
    if (in_sizes[10] == NLAYERS * DIM) {
        Wq = (const float*)d_in[9];  bq = (const float*)d_in[10];
        Wk = (const float*)d_in[11]; bk = (const float*)d_in[12];
        Wv = (const float*)d_in[13]; bv = (const float*)d_in[14];
        Wo = (const float*)d_in[15]; bo = (const float*)d_in[16];
    } else {
        Wq = (const float*)d_in[9];  Wk = (const float*)d_in[10];
        Wv = (const float*)d_in[11]; Wo = (const float*)d_in[12];
        bq = (const float*)d_in[13]; bk = (const float*)d_in[14];
        bv = (const float*)d_in[15]; bo = (const float*)d_in[16];
    }
    const float* W1  = (const float*)d_in[17];
    const float* b1  = (const float*)d_in[18];
    const float* W2  = (const float*)d_in[19];
    const float* b2  = (const float*)d_in[20];
    const float* gm1 = (const float*)d_in[21];
    const float* be1 = (const float*)d_in[22];
    const float* gm2 = (const float*)d_in[23];
    const float* be2 = (const float*)d_in[24];
    const float* Wm1 = (const float*)d_in[25];
    const float* bm1 = (const float*)d_in[26];
    const float* Wm2 = (const float*)d_in[27];
    const float* bm2 = (const float*)d_in[28];

    static float *h = nullptr, *h2, *qkv, *ob, *bqkv;
    static __nv_bfloat16 *xhi, *xlo, *fhi, *flo;
    static __nv_bfloat16 *wqkvh, *wqkvl, *woh, *wol, *w1h, *w1l, *w2h, *w2l;
    if (!h) {
        cudaGetSymbolAddress((void**)&h,    g_h);
        cudaGetSymbolAddress((void**)&h2,   g_h2);
        cudaGetSymbolAddress((void**)&qkv,  g_qkv);
        cudaGetSymbolAddress((void**)&ob,   g_o);
        cudaGetSymbolAddress((void**)&bqkv, g_bqkv);
        cudaGetSymbolAddress((void**)&xhi,  g_xhi);
        cudaGetSymbolAddress((void**)&xlo,  g_xlo);
        cudaGetSymbolAddress((void**)&fhi,  g_fhi);
        cudaGetSymbolAddress((void**)&flo,  g_flo);
        cudaGetSymbolAddress((void**)&wqkvh, g_wqkv_hi);
        cudaGetSymbolAddress((void**)&wqkvl, g_wqkv_lo);
        cudaGetSymbolAddress((void**)&woh,  g_wo_hi);
        cudaGetSymbolAddress((void**)&wol,  g_wo_lo);
        cudaGetSymbolAddress((void**)&w1h,  g_w1_hi);
        cudaGetSymbolAddress((void**)&w1l,  g_w1_lo);
        cudaGetSymbolAddress((void**)&w2h,  g_w2_hi);
        cudaGetSymbolAddress((void**)&w2l,  g_w2_lo);
        cudaFuncSetAttribute(attn_kernel,
            cudaFuncAttributeMaxDynamicSharedMemorySize,
            ATT_SMEM_FLOATS * (int)sizeof(float));
        cudaFuncSetAttribute(gemm_mma_kernel,
            cudaFuncAttributeMaxDynamicSharedMemorySize, GSM_TOTAL);
    }
    const int attSmem = ATT_SMEM_FLOATS * (int)sizeof(float);

    // precompute
    init_h_kernel<<<NROWS * DIM / 256, 256>>>(cell_types, cell_emb);
    prep_kernel<<<BSZ * SEQ * SEQ / 256, 256>>>(dist, Kkr);
    pack_bqkv_kernel<<<NLAYERS * QKVN / 256, 256>>>(bq, bk, bv);

    cvt_w_kernel<<<dim3(DIM/32, DIM/32, NLAYERS), 256>>>(Wq, wqkvh,             wqkvl,             DIM, DIM, (size_t)DIM*DIM, (size_t)QKVN*DIM);
    cvt_w_kernel<<<dim3(DIM/32, DIM/32, NLAYERS), 256>>>(Wk, wqkvh + DIM*DIM,   wqkvl + DIM*DIM,   DIM, DIM, (size_t)DIM*DIM, (size_t)QKVN*DIM);
    cvt_w_kernel<<<dim3(DIM/32, DIM/32, NLAYERS), 256>>>(Wv, wqkvh + 2*DIM*DIM, wqkvl + 2*DIM*DIM, DIM, DIM, (size_t)DIM*DIM, (size_t)QKVN*DIM);
    cvt_w_kernel<<<dim3(DIM/32, DIM/32, NLAYERS), 256>>>(Wo, woh, wol, DIM, DIM, (size_t)DIM*DIM, (size_t)DIM*DIM);
    cvt_w_kernel<<<dim3(FFD/32, DIM/32, NLAYERS), 256>>>(W1, w1h, w1l, DIM, FFD, (size_t)DIM*FFD, (size_t)DIM*FFD);
    cvt_w_kernel<<<dim3(DIM/32, FFD/32, NLAYERS), 256>>>(W2, w2h, w2l, FFD, DIM, (size_t)DIM*FFD, (size_t)DIM*FFD);

    dim3 gQKV(QKVN / 64, NROWS / 128);
    dim3 gD(DIM / 64, NROWS / 128);
    dim3 gF(FFD / 64, NROWS / 128);
    dim3 gAtt(BSZ * NHEAD, SEQ / 64);

    for (int li = 0; li < NLAYERS; li++) {
        const __nv_bfloat16* lwqh = wqkvh + (size_t)li * QKVN * DIM;
        const __nv_bfloat16* lwql = wqkvl + (size_t)li * QKVN * DIM;
        const __nv_bfloat16* lwoh = woh + (size_t)li * DIM * DIM;
        const __nv_bfloat16* lwol = wol + (size_t)li * DIM * DIM;
        const __nv_bfloat16* lw1h = w1h + (size_t)li * FFD * DIM;
        const __nv_bfloat16* lw1l = w1l + (size_t)li * FFD * DIM;
        const __nv_bfloat16* lw2h = w2h + (size_t)li * DIM * FFD;
        const __nv_bfloat16* lw2l = w2l + (size_t)li * DIM * FFD;

        gemm_mma_kernel<<<gQKV, 256, GSM_TOTAL>>>(xhi, xlo, lwqh, lwql,
            bqkv + (size_t)li * QKVN, qkv, nullptr, nullptr, QKVN, DIM, 0);

        attn_kernel<<<gAtt, 256, attSmem>>>(Kqk, Kqr, Vqk, Vqr, Vkr);

        gemm_mma_kernel<<<gD, 256, GSM_TOTAL>>>(xhi, xlo, lwoh, lwol,
            bo + li * DIM, ob, nullptr, nullptr, DIM, DIM, 0);
        add_ln_kernel<<<NROWS / 8, 256>>>(h, ob, gm1 + li * DIM, be1 + li * DIM, h2);

        gemm_mma_kernel<<<gF, 256, GSM_TOTAL>>>(xhi, xlo, lw1h, lw1l,
            b1 + li * FFD, nullptr, fhi, flo, FFD, DIM, 2);

        gemm_mma_kernel<<<gD, 256, GSM_TOTAL>>>(fhi, flo, lw2h, lw2l,
            b2 + li * DIM, ob, nullptr, nullptr, DIM, FFD, 0);
        add_ln_kernel<<<NROWS / 8, 256>>>(h2, ob, gm2 + li * DIM, be2 + li * DIM, h);
    }

    head_kernel<<<BSZ, 256>>>(Wm1, bm1, Wm2, bm2, (float*)d_out);
}

// round 8
// speedup vs baseline: 1.0226x; 1.0226x over previous
#include <cuda_runtime.h>
#include <cuda_bf16.h>
#include <math.h>
#include <stdint.h>

// ---------------------------------------------------------------------------
// CellMatesTransformer forward. mma.sync bf16 split GEMMs.
// R8 = R7 resubmit (infra flake): R5 2-stage pipeline + 2 CTAs/SM,
// term-major MMA order, warp-LN.
// ---------------------------------------------------------------------------

#define NLAYERS 8
#define BSZ     4
#define SEQ     512
#define DIM     512
#define NHEAD   16
#define KHD     32
#define FFD     2048
#define NDB     14
#define NROWS   (BSZ*SEQ)      // 2048
#define QKVN    (3*DIM)        // 1536

#define ATT_SCALE 0.17677669529663687f   // 1/sqrt(32)

// ------------------------- scratch (device globals) ------------------------
__device__ float g_h  [NROWS*DIM];
__device__ float g_h2 [NROWS*DIM];
__device__ float g_qkv[NROWS*QKVN];
__device__ float g_o  [NROWS*DIM];
__device__ unsigned char g_didx[BSZ*SEQ*SEQ];
__device__ float g_ekr [BSZ*SEQ*SEQ];

// split activations
__device__ __nv_bfloat16 g_xhi[NROWS*DIM];
__device__ __nv_bfloat16 g_xlo[NROWS*DIM];
__device__ __nv_bfloat16 g_fhi[NROWS*FFD];
__device__ __nv_bfloat16 g_flo[NROWS*FFD];

// split weights (pre-transposed, K-major)
__device__ __nv_bfloat16 g_wqkv_hi[NLAYERS*QKVN*DIM];
__device__ __nv_bfloat16 g_wqkv_lo[NLAYERS*QKVN*DIM];
__device__ __nv_bfloat16 g_wo_hi[NLAYERS*DIM*DIM];
__device__ __nv_bfloat16 g_wo_lo[NLAYERS*DIM*DIM];
__device__ __nv_bfloat16 g_w1_hi[NLAYERS*FFD*DIM];
__device__ __nv_bfloat16 g_w1_lo[NLAYERS*FFD*DIM];
__device__ __nv_bfloat16 g_w2_hi[NLAYERS*DIM*FFD];
__device__ __nv_bfloat16 g_w2_lo[NLAYERS*DIM*FFD];
__device__ float g_bqkv[NLAYERS*QKVN];

// ------------------------- PTX helpers --------------------------------------

__device__ __forceinline__ uint32_t smem_u32(const void* p) {
    uint32_t a;
    asm("{ .reg .u64 t; cvta.to.shared.u64 t, %1; cvt.u32.u64 %0, t; }" : "=r"(a) : "l"(p));
    return a;
}
#define SW128(off) ((off) ^ (((off) >> 3) & 0x70))

#define CP_ASYNC16(sm, gp) \
    asm volatile("cp.async.cg.shared.global [%0], [%1], 16;" :: "r"(sm), "l"(gp) : "memory")
#define CP_COMMIT() asm volatile("cp.async.commit_group;" ::: "memory")

#define LDSM4(r0, r1, r2, r3, addr) \
    asm volatile("ldmatrix.sync.aligned.m8n8.x4.shared.b16 {%0,%1,%2,%3}, [%4];" \
        : "=r"(r0), "=r"(r1), "=r"(r2), "=r"(r3) : "r"(addr))

#define MMA16816(c, a, b0, b1) \
    asm volatile("mma.sync.aligned.m16n8k16.row.col.f32.bf16.bf16.f32 " \
        "{%0,%1,%2,%3}, {%4,%5,%6,%7}, {%8,%9}, {%0,%1,%2,%3};" \
        : "+f"((c)[0]), "+f"((c)[1]), "+f"((c)[2]), "+f"((c)[3]) \
        : "r"((a)[0]), "r"((a)[1]), "r"((a)[2]), "r"((a)[3]), "r"(b0), "r"(b1))

__device__ __forceinline__ void split_bf16(float v, __nv_bfloat16& h, __nv_bfloat16& l) {
    h = __float2bfloat16(v);
    l = __float2bfloat16(v - __bfloat162float(h));
}

// ------------------------- precompute kernels ------------------------------

__global__ __launch_bounds__(256) void init_h_kernel(
    const int* __restrict__ cell_types, const float* __restrict__ cell_emb)
{
    int i = blockIdx.x * 256 + threadIdx.x;
    int row = i >> 9, d = i & 511;
    float v = cell_emb[cell_types[row] * DIM + d];
    g_h[i] = v;
    split_bf16(v, g_xhi[i], g_xlo[i]);
}

__global__ __launch_bounds__(256) void prep_kernel(
    const float* __restrict__ dist, const float* __restrict__ Kkr)
{
    __shared__ float ksum[NDB];
    if (threadIdx.x < NDB) {
        float s = 0.f;
        #pragma unroll
        for (int kk = 0; kk < KHD; kk++) s += Kkr[threadIdx.x * KHD + kk];
        ksum[threadIdx.x] = s;
    }
    __syncthreads();
    int i = blockIdx.x * 256 + threadIdx.x;
    float dv = dist[i];
    int idx = 0;
    #pragma unroll
    for (int j = 1; j <= NDB; j++) idx += (dv > 10.0f * (float)j);
    if (idx > NDB - 1) idx = NDB - 1;
    g_didx[i] = (unsigned char)idx;
    g_ekr[i]  = ksum[idx];
}

// weight transpose + split, batched over layers (grid.z)
__global__ __launch_bounds__(256) void cvt_w_kernel(
    const float* __restrict__ W, __nv_bfloat16* __restrict__ hi,
    __nv_bfloat16* __restrict__ lo, int K, int N,
    size_t srcStride, size_t dstStride)
{
    __shared__ float t[32][33];
    const float* Ws = W + (size_t)blockIdx.z * srcStride;
    __nv_bfloat16* hid = hi + (size_t)blockIdx.z * dstStride;
    __nv_bfloat16* lod = lo + (size_t)blockIdx.z * dstStride;
    int k0 = blockIdx.y * 32, n0 = blockIdx.x * 32;
    int tx = threadIdx.x & 31, ty = threadIdx.x >> 5;
    #pragma unroll
    for (int r = 0; r < 4; r++)
        t[ty + 8 * r][tx] = Ws[(size_t)(k0 + ty + 8 * r) * N + n0 + tx];
    __syncthreads();
    #pragma unroll
    for (int r = 0; r < 4; r++) {
        int n = n0 + ty + 8 * r, k = k0 + tx;
        float v = t[tx][ty + 8 * r];
        __nv_bfloat16 h, l;
        split_bf16(v, h, l);
        hid[(size_t)n * K + k] = h;
        lod[(size_t)n * K + k] = l;
    }
}

__global__ __launch_bounds__(256) void pack_bqkv_kernel(
    const float* __restrict__ bq, const float* __restrict__ bk,
    const float* __restrict__ bv)
{
    int i = blockIdx.x * 256 + threadIdx.x;
    int li = i / QKVN, j = i % QKVN;
    float v;
    if (j < DIM)            v = bq[li * DIM + j];
    else if (j < 2 * DIM)   v = bk[li * DIM + j - DIM];
    else                    v = bv[li * DIM + j - 2 * DIM];
    g_bqkv[i] = v;
}

// ------------------------- mma.sync GEMM ------------------------------------
// CTA tile 128 x 64, 256 thr (4x2 warps, 32x32 warp tiles).
// 2-stage cp.async pipeline (2 CTAs/SM), K chunks of 64, term-major MMA order.
// mode 0: fp32 out.  mode 2: exact-GELU + split bf16 out.

#define GSM_BUF   49152
#define GSM_TOTAL (2*GSM_BUF)

__device__ __forceinline__ void load_chunk(
    uint32_t base, int tid,
    const __nv_bfloat16* Ahi, const __nv_bfloat16* Alo,
    const __nv_bfloat16* Bhi, const __nv_bfloat16* Blo,
    int rowBase, int colBase, int K, int k0)
{
    #pragma unroll
    for (int t = 0; t < 4; t++) {
        int idx = tid + (t << 8);
        int r = idx >> 3, seg = idx & 7;
        uint32_t so = SW128((uint32_t)(r * 128 + seg * 16));
        size_t goff = (size_t)(rowBase + r) * K + k0 + seg * 8;
        CP_ASYNC16(base + so,         Ahi + goff);
        CP_ASYNC16(base + 16384 + so, Alo + goff);
    }
    #pragma unroll
    for (int t = 0; t < 2; t++) {
        int idx = tid + (t << 8);
        int r = idx >> 3, seg = idx & 7;
        uint32_t so = SW128((uint32_t)(r * 128 + seg * 16));
        size_t goff = (size_t)(colBase + r) * K + k0 + seg * 8;
        CP_ASYNC16(base + 32768 + so, Bhi + goff);
        CP_ASYNC16(base + 40960 + so, Blo + goff);
    }
}

struct Frags {
    uint32_t ah[2][4], al[2][4], bh[2][4], bl[2][4];
};

__device__ __forceinline__ void load_frags(
    uint32_t base, int wr, int wc, int rA, int hs, int ks, Frags& f)
{
    int segoff = (ks * 2 + hs) * 16;
    #pragma unroll
    for (int mt = 0; mt < 2; mt++) {
        int row = wr * 32 + mt * 16 + rA;
        uint32_t off = SW128((uint32_t)(row * 128 + segoff));
        LDSM4(f.ah[mt][0], f.ah[mt][1], f.ah[mt][2], f.ah[mt][3], base + off);
        LDSM4(f.al[mt][0], f.al[mt][1], f.al[mt][2], f.al[mt][3], base + 16384 + off);
    }
    #pragma unroll
    for (int g = 0; g < 2; g++) {
        int row = wc * 32 + g * 16 + rA;
        uint32_t off = SW128((uint32_t)(row * 128 + segoff));
        LDSM4(f.bh[g][0], f.bh[g][1], f.bh[g][2], f.bh[g][3], base + 32768 + off);
        LDSM4(f.bl[g][0], f.bl[g][1], f.bl[g][2], f.bl[g][3], base + 40960 + off);
    }
}

__device__ __forceinline__ void mma_frags(float acc[2][4][4], const Frags& f)
{
    // term-major: same-acc RAW pairs are 8 independent MMAs apart
    #pragma unroll
    for (int mt = 0; mt < 2; mt++)
        #pragma unroll
        for (int nt = 0; nt < 4; nt++) {
            int g = nt >> 1, s = nt & 1;
            MMA16816(acc[mt][nt], f.ah[mt], f.bh[g][s], f.bh[g][s + 2]);
        }
    #pragma unroll
    for (int mt = 0; mt < 2; mt++)
        #pragma unroll
        for (int nt = 0; nt < 4; nt++) {
            int g = nt >> 1, s = nt & 1;
            MMA16816(acc[mt][nt], f.ah[mt], f.bl[g][s], f.bl[g][s + 2]);
        }
    #pragma unroll
    for (int mt = 0; mt < 2; mt++)
        #pragma unroll
        for (int nt = 0; nt < 4; nt++) {
            int g = nt >> 1, s = nt & 1;
            MMA16816(acc[mt][nt], f.al[mt], f.bh[g][s], f.bh[g][s + 2]);
        }
}

__global__ __launch_bounds__(256, 2) void gemm_mma_kernel(
    const __nv_bfloat16* __restrict__ Ahi, const __nv_bfloat16* __restrict__ Alo,
    const __nv_bfloat16* __restrict__ Bhi, const __nv_bfloat16* __restrict__ Blo,
    const float* __restrict__ bias, float* __restrict__ C,
    __nv_bfloat16* __restrict__ Chi, __nv_bfloat16* __restrict__ Clo,
    int N, int K, int mode)
{
    extern __shared__ char smem[];
    uint32_t sb = smem_u32(smem);
    int tid = threadIdx.x, wid = tid >> 5, lane = tid & 31;
    int wr = wid >> 1, wc = wid & 1;
    int rowBase = blockIdx.y * 128, colBase = blockIdx.x * 64;
    int S = K >> 6;
    int rA = lane & 15, hs = lane >> 4;

    float acc[2][4][4];
    #pragma unroll
    for (int mt = 0; mt < 2; mt++)
        #pragma unroll
        for (int nt = 0; nt < 4; nt++)
            #pragma unroll
            for (int e = 0; e < 4; e++) acc[mt][nt][e] = 0.f;

    load_chunk(sb, tid, Ahi, Alo, Bhi, Blo, rowBase, colBase, K, 0);
    CP_COMMIT();

    for (int i = 0; i < S; i++) {
        if (i + 1 < S) {
            load_chunk(sb + ((i + 1) & 1) * GSM_BUF, tid,
                       Ahi, Alo, Bhi, Blo, rowBase, colBase, K, (i + 1) << 6);
            CP_COMMIT();
            asm volatile("cp.async.wait_group 1;" ::: "memory");
        } else {
            asm volatile("cp.async.wait_group 0;" ::: "memory");
        }
        __syncthreads();

        uint32_t base = sb + (i & 1) * GSM_BUF;
        #pragma unroll
        for (int ks = 0; ks < 4; ks++) {
            Frags f;
            load_frags(base, wr, wc, rA, hs, ks, f);
            mma_frags(acc, f);
        }
        __syncthreads();
    }

    int tg = lane >> 2, tq = lane & 3;
    #pragma unroll
    for (int mt = 0; mt < 2; mt++) {
        #pragma unroll
        for (int nt = 0; nt < 4; nt++) {
            int c0 = colBase + wc * 32 + nt * 8 + tq * 2;
            float b0 = bias[c0], b1 = bias[c0 + 1];
            int r0 = rowBase + wr * 32 + mt * 16 + tg;
            float v00 = acc[mt][nt][0] + b0, v01 = acc[mt][nt][1] + b1;
            float v10 = acc[mt][nt][2] + b0, v11 = acc[mt][nt][3] + b1;
            if (mode == 2) {
                v00 = 0.5f * v00 * (1.0f + erff(v00 * 0.70710678118654752f));
                v01 = 0.5f * v01 * (1.0f + erff(v01 * 0.70710678118654752f));
                v10 = 0.5f * v10 * (1.0f + erff(v10 * 0.70710678118654752f));
                v11 = 0.5f * v11 * (1.0f + erff(v11 * 0.70710678118654752f));
                __nv_bfloat162 h0, l0, h1, l1;
                split_bf16(v00, h0.x, l0.x); split_bf16(v01, h0.y, l0.y);
                split_bf16(v10, h1.x, l1.x); split_bf16(v11, h1.y, l1.y);
                *(__nv_bfloat162*)&Chi[(size_t)r0 * N + c0]       = h0;
                *(__nv_bfloat162*)&Clo[(size_t)r0 * N + c0]       = l0;
                *(__nv_bfloat162*)&Chi[(size_t)(r0 + 8) * N + c0] = h1;
                *(__nv_bfloat162*)&Clo[(size_t)(r0 + 8) * N + c0] = l1;
            } else {
                *(float2*)&C[(size_t)r0 * N + c0]       = make_float2(v00, v01);
                *(float2*)&C[(size_t)(r0 + 8) * N + c0] = make_float2(v10, v11);
            }
        }
    }
}

// ------------------------- attention ----------------------------------------

#define ATT_SMEM_FLOATS (32*512 + 512*32 + 14*512 + 8*512 + 448*3 + 8*16)

__global__ __launch_bounds__(256) void attn_kernel(
    const float* __restrict__ Kqk, const float* __restrict__ Kqr,
    const float* __restrict__ Vqk, const float* __restrict__ Vqr,
    const float* __restrict__ Vkr)
{
    extern __shared__ float sm[];
    float* Kt    = sm;
    float* Vs    = Kt + 32 * 512;
    float* kEt   = Vs + 512 * 32;
    float* ps    = kEt + 14 * 512;
    float* tKqkT = ps + 8 * 512;
    float* tKqr  = tKqkT + 448;
    float* tVs   = tKqr + 448;
    float* wb    = tVs + 448;

    int bh = blockIdx.x;
    int b = bh >> 4, h = bh & 15;
    int tid = threadIdx.x, lane = tid & 31, warp = tid >> 5;

    const float* qb = g_qkv + ((size_t)b * SEQ) * QKVN + h * KHD;
    const float* kb = qb + DIM;
    const float* vb = qb + 2 * DIM;

    for (int i = tid; i < NDB * KHD; i += 256) {
        int d = i / KHD, kk = i % KHD;
        tKqkT[kk * NDB + d] = Kqk[i];
        tKqr[i] = Kqr[i];
        tVs[i]  = Vqk[i] + Vqr[i] + Vkr[i];
    }
    for (int i = tid; i < SEQ * 8; i += 256) {
        int x = i >> 3, g = (i & 7) << 2;
        float4 k4 = *(const float4*)&kb[(size_t)x * QKVN + g];
        Kt[(g + 0) * SEQ + x] = k4.x; Kt[(g + 1) * SEQ + x] = k4.y;
        Kt[(g + 2) * SEQ + x] = k4.z; Kt[(g + 3) * SEQ + x] = k4.w;
        float4 v4 = *(const float4*)&vb[(size_t)x * QKVN + g];
        *(float4*)&Vs[x * KHD + g] = v4;
    }
    __syncthreads();

    for (int i = tid; i < NDB * SEQ; i += 256) {
        int d = i >> 9, x = i & 511;
        float s = 0.f;
        #pragma unroll
        for (int kk = 0; kk < KHD; kk++)
            s = fmaf(Kt[kk * SEQ + x], tKqr[d * KHD + kk], s);
        kEt[i] = s;
    }
    __syncthreads();

    int l0 = blockIdx.y * 64 + warp * 8;
    for (int r = 0; r < 8; r++) {
        int l = l0 + r;
        float qreg = qb[(size_t)l * QKVN + lane];
        float e[16];
        #pragma unroll
        for (int j = 0; j < 16; j++) e[j] = 0.f;
        float qE = 0.f;
        #pragma unroll
        for (int kk = 0; kk < KHD; kk++) {
            float qk = __shfl_sync(0xffffffffu, qreg, kk);
            #pragma unroll
            for (int j = 0; j < 16; j++)
                e[j] = fmaf(qk, Kt[kk * SEQ + lane + j * 32], e[j]);
            if (lane < NDB) qE = fmaf(qk, tKqkT[kk * NDB + lane], qE);
        }

        const unsigned char* drow = &g_didx[((size_t)b * SEQ + l) * SEQ];
        const float*         erow = &g_ekr [((size_t)b * SEQ + l) * SEQ];
        int dly[16];
        float m = -1e30f;
        #pragma unroll
        for (int j = 0; j < 16; j++) {
            int x = lane + j * 32;
            int d = drow[x];
            dly[j] = d;
            float biasv = __shfl_sync(0xffffffffu, qE, d) + kEt[d * SEQ + x] + erow[x];
            e[j] = (e[j] + biasv) * ATT_SCALE;
            m = fmaxf(m, e[j]);
        }
        #pragma unroll
        for (int off = 16; off; off >>= 1)
            m = fmaxf(m, __shfl_xor_sync(0xffffffffu, m, off));

        if (lane < 16) wb[warp * 16 + lane] = 0.f;
        __syncwarp();

        float sum = 0.f;
        float pj[16];
        #pragma unroll
        for (int j = 0; j < 16; j++) {
            float p = expf(e[j] - m);
            pj[j] = p;
            sum += p;
            ps[warp * SEQ + lane + j * 32] = p;
        }
        #pragma unroll
        for (int off = 16; off; off >>= 1)
            sum += __shfl_xor_sync(0xffffffffu, sum, off);
        #pragma unroll
        for (int j = 0; j < 16; j++)
            atomicAdd(&wb[warp * 16 + dly[j]], pj[j]);
        __syncwarp();

        float acc = 0.f;
        const float* pw = &ps[warp * SEQ];
        for (int x = 0; x < SEQ; x += 4) {
            float4 p4 = *(const float4*)&pw[x];
            acc = fmaf(p4.x, Vs[(x + 0) * KHD + lane], acc);
            acc = fmaf(p4.y, Vs[(x + 1) * KHD + lane], acc);
            acc = fmaf(p4.z, Vs[(x + 2) * KHD + lane], acc);
            acc = fmaf(p4.w, Vs[(x + 3) * KHD + lane], acc);
        }
        #pragma unroll
        for (int d = 0; d < NDB; d++)
            acc = fmaf(wb[warp * 16 + d], tVs[d * KHD + lane], acc);

        float z = acc / sum;
        size_t oidx = ((size_t)b * SEQ + l) * DIM + h * KHD + lane;
        split_bf16(z, g_xhi[oidx], g_xlo[oidx]);
    }
}

// ------------------------- residual + layernorm (warp per row) --------------

__global__ __launch_bounds__(256) void add_ln_kernel(
    const float* __restrict__ x, const float* __restrict__ y,
    const float* __restrict__ g, const float* __restrict__ b,
    float* __restrict__ out)
{
    int warp = threadIdx.x >> 5, lane = threadIdx.x & 31;
    int row = blockIdx.x * 8 + warp;
    const float* xr = x + (size_t)row * DIM;
    const float* yr = y + (size_t)row * DIM;
    int c0 = lane * 16;

    float v[16];
    float s = 0.f, s2 = 0.f;
    #pragma unroll
    for (int j = 0; j < 16; j += 4) {
        float4 a4 = *(const float4*)&xr[c0 + j];
        float4 b4 = *(const float4*)&yr[c0 + j];
        v[j + 0] = a4.x + b4.x; v[j + 1] = a4.y + b4.y;
        v[j + 2] = a4.z + b4.z; v[j + 3] = a4.w + b4.w;
        #pragma unroll
        for (int q = 0; q < 4; q++) { s += v[j + q]; s2 += v[j + q] * v[j + q]; }
    }
    #pragma unroll
    for (int off = 16; off; off >>= 1) {
        s  += __shfl_xor_sync(0xffffffffu, s,  off);
        s2 += __shfl_xor_sync(0xffffffffu, s2, off);
    }
    float mu = s * (1.0f / 512.0f);
    float var = s2 * (1.0f / 512.0f) - mu * mu;
    float rs = rsqrtf(var + 1e-5f);

    size_t base = (size_t)row * DIM + c0;
    #pragma unroll
    for (int j = 0; j < 16; j++) {
        float o = (v[j] - mu) * rs * g[c0 + j] + b[c0 + j];
        out[base + j] = o;
        split_bf16(o, g_xhi[base + j], g_xlo[base + j]);
    }
}

// ------------------------- pooling + MLP head ------------------------------

__global__ __launch_bounds__(256) void head_kernel(
    const float* __restrict__ Wm1, const float* __restrict__ bm1,
    const float* __restrict__ Wm2, const float* __restrict__ bm2,
    float* __restrict__ out)
{
    __shared__ float pooled[DIM];
    __shared__ float hidden[DIM];
    __shared__ float red[256];
    int b = blockIdx.x, t = threadIdx.x;
    const float* hb = g_h + (size_t)b * SEQ * DIM;
    for (int d = t; d < DIM; d += 256) {
        float s = 0.f;
        for (int l = 0; l < SEQ; l++) s += hb[(size_t)l * DIM + d];
        pooled[d] = s;
    }
    __syncthreads();
    for (int m = t; m < DIM; m += 256) {
        float s = bm1[m];
        for (int kd = 0; kd < DIM; kd++)
            s = fmaf(pooled[kd], Wm1[(size_t)kd * DIM + m], s);
        hidden[m] = fmaxf(s, 0.f);
    }
    __syncthreads();
    red[t] = hidden[t] * Wm2[t] + hidden[t + 256] * Wm2[t + 256];
    __syncthreads();
    for (int s = 128; s; s >>= 1) { if (t < s) red[t] += red[t + s]; __syncthreads(); }
    if (t == 0) out[b] = red[0] + bm2[0];
}

// ------------------------- launcher ----------------------------------------

extern "C" void kernel_launch(void* const* d_in, const int* in_sizes, int n_in,
                              void* d_out, int out_size)
{
    (void)n_in; (void)out_size;

    const int*   cell_types = (const int*)  d_in[0];
    const float* dist       = (const float*)d_in[1];
    const float* cell_emb   = (const float*)d_in[2];
    const float* Kqk = (const float*)d_in[3];
    const float* Kqr = (const float*)d_in[4];
    const float* Kkr = (const float*)d_in[5];
    const float* Vqk = (const float*)d_in[6];
    const float* Vqr = (const float*)d_in[7];
    const float* Vkr = (const float*)d_in[8];

    const float *Wq, *bq, *Wk, *bk, *Wv, *bv, *Wo, *bo;
    if (in_sizes[10] == NLAYERS * DIM) {
        Wq = (const float*)d_in[9];  bq = (const float*)d_in[10];
        Wk = (const float*)d_in[11]; bk = (const float*)d_in[12];
        Wv = (const float*)d_in[13]; bv = (const float*)d_in[14];
        Wo = (const float*)d_in[15]; bo = (const float*)d_in[16];
    } else {
        Wq = (const float*)d_in[9];  Wk = (const float*)d_in[10];
        Wv = (const float*)d_in[11]; Wo = (const float*)d_in[12];
        bq = (const float*)d_in[13]; bk = (const float*)d_in[14];
        bv = (const float*)d_in[15]; bo = (const float*)d_in[16];
    }
    const float* W1  = (const float*)d_in[17];
    const float* b1  = (const float*)d_in[18];
    const float* W2  = (const float*)d_in[19];
    const float* b2  = (const float*)d_in[20];
    const float* gm1 = (const float*)d_in[21];
    const float* be1 = (const float*)d_in[22];
    const float* gm2 = (const float*)d_in[23];
    const float* be2 = (const float*)d_in[24];
    const float* Wm1 = (const float*)d_in[25];
    const float* bm1 = (const float*)d_in[26];
    const float* Wm2 = (const float*)d_in[27];
    const float* bm2 = (const float*)d_in[28];

    static float *h = nullptr, *h2, *qkv, *ob, *bqkv;
    static __nv_bfloat16 *xhi, *xlo, *fhi, *flo;
    static __nv_bfloat16 *wqkvh, *wqkvl, *woh, *wol, *w1h, *w1l, *w2h, *w2l;
    if (!h) {
        cudaGetSymbolAddress((void**)&h,    g_h);
        cudaGetSymbolAddress((void**)&h2,   g_h2);
        cudaGetSymbolAddress((void**)&qkv,  g_qkv);
        cudaGetSymbolAddress((void**)&ob,   g_o);
        cudaGetSymbolAddress((void**)&bqkv, g_bqkv);
        cudaGetSymbolAddress((void**)&xhi,  g_xhi);
        cudaGetSymbolAddress((void**)&xlo,  g_xlo);
        cudaGetSymbolAddress((void**)&fhi,  g_fhi);
        cudaGetSymbolAddress((void**)&flo,  g_flo);
        cudaGetSymbolAddress((void**)&wqkvh, g_wqkv_hi);
        cudaGetSymbolAddress((void**)&wqkvl, g_wqkv_lo);
        cudaGetSymbolAddress((void**)&woh,  g_wo_hi);
        cudaGetSymbolAddress((void**)&wol,  g_wo_lo);
        cudaGetSymbolAddress((void**)&w1h,  g_w1_hi);
        cudaGetSymbolAddress((void**)&w1l,  g_w1_lo);
        cudaGetSymbolAddress((void**)&w2h,  g_w2_hi);
        cudaGetSymbolAddress((void**)&w2l,  g_w2_lo);
        cudaFuncSetAttribute(attn_kernel,
            cudaFuncAttributeMaxDynamicSharedMemorySize,
            ATT_SMEM_FLOATS * (int)sizeof(float));
        cudaFuncSetAttribute(gemm_mma_kernel,
            cudaFuncAttributeMaxDynamicSharedMemorySize, GSM_TOTAL);
    }
    const int attSmem = ATT_SMEM_FLOATS * (int)sizeof(float);

    // precompute
    init_h_kernel<<<NROWS * DIM / 256, 256>>>(cell_types, cell_emb);
    prep_kernel<<<BSZ * SEQ * SEQ / 256, 256>>>(dist, Kkr);
    pack_bqkv_kernel<<<NLAYERS * QKVN / 256, 256>>>(bq, bk, bv);

    cvt_w_kernel<<<dim3(DIM/32, DIM/32, NLAYERS), 256>>>(Wq, wqkvh,             wqkvl,             DIM, DIM, (size_t)DIM*DIM, (size_t)QKVN*DIM);
    cvt_w_kernel<<<dim3(DIM/32, DIM/32, NLAYERS), 256>>>(Wk, wqkvh + DIM*DIM,   wqkvl + DIM*DIM,   DIM, DIM, (size_t)DIM*DIM, (size_t)QKVN*DIM);
    cvt_w_kernel<<<dim3(DIM/32, DIM/32, NLAYERS), 256>>>(Wv, wqkvh + 2*DIM*DIM, wqkvl + 2*DIM*DIM, DIM, DIM, (size_t)DIM*DIM, (size_t)QKVN*DIM);
    cvt_w_kernel<<<dim3(DIM/32, DIM/32, NLAYERS), 256>>>(Wo, woh, wol, DIM, DIM, (size_t)DIM*DIM, (size_t)DIM*DIM);
    cvt_w_kernel<<<dim3(FFD/32, DIM/32, NLAYERS), 256>>>(W1, w1h, w1l, DIM, FFD, (size_t)DIM*FFD, (size_t)DIM*FFD);
    cvt_w_kernel<<<dim3(DIM/32, FFD/32, NLAYERS), 256>>>(W2, w2h, w2l, FFD, DIM, (size_t)DIM*FFD, (size_t)DIM*FFD);

    dim3 gQKV(QKVN / 64, NROWS / 128);
    dim3 gD(DIM / 64, NROWS / 128);
    dim3 gF(FFD / 64, NROWS / 128);
    dim3 gAtt(BSZ * NHEAD, SEQ / 64);

    for (int li = 0; li < NLAYERS; li++) {
        const __nv_bfloat16* lwqh = wqkvh + (size_t)li * QKVN * DIM;
        const __nv_bfloat16* lwql = wqkvl + (size_t)li * QKVN * DIM;
        const __nv_bfloat16* lwoh = woh + (size_t)li * DIM * DIM;
        const __nv_bfloat16* lwol = wol + (size_t)li * DIM * DIM;
        const __nv_bfloat16* lw1h = w1h + (size_t)li * FFD * DIM;
        const __nv_bfloat16* lw1l = w1l + (size_t)li * FFD * DIM;
        const __nv_bfloat16* lw2h = w2h + (size_t)li * DIM * FFD;
        const __nv_bfloat16* lw2l = w2l + (size_t)li * DIM * FFD;

        gemm_mma_kernel<<<gQKV, 256, GSM_TOTAL>>>(xhi, xlo, lwqh, lwql,
            bqkv + (size_t)li * QKVN, qkv, nullptr, nullptr, QKVN, DIM, 0);

        attn_kernel<<<gAtt, 256, attSmem>>>(Kqk, Kqr, Vqk, Vqr, Vkr);

        gemm_mma_kernel<<<gD, 256, GSM_TOTAL>>>(xhi, xlo, lwoh, lwol,
            bo + li * DIM, ob, nullptr, nullptr, DIM, DIM, 0);
        add_ln_kernel<<<NROWS / 8, 256>>>(h, ob, gm1 + li * DIM, be1 + li * DIM, h2);

        gemm_mma_kernel<<<gF, 256, GSM_TOTAL>>>(xhi, xlo, lw1h, lw1l,
            b1 + li * FFD, nullptr, fhi, flo, FFD, DIM, 2);

        gemm_mma_kernel<<<gD, 256, GSM_TOTAL>>>(fhi, flo, lw2h, lw2l,
            b2 + li * DIM, ob, nullptr, nullptr, DIM, FFD, 0);
        add_ln_kernel<<<NROWS / 8, 256>>>(h2, ob, gm2 + li * DIM, be2 + li * DIM, h);
    }

    head_kernel<<<BSZ, 256>>>(Wm1, bm1, Wm2, bm2, (float*)d_out);
}

// round 10
// speedup vs baseline: 1.0854x; 1.0614x over previous
#include <cuda_runtime.h>
#include <cuda_bf16.h>
#include <math.h>
#include <stdint.h>

// ---------------------------------------------------------------------------
// CellMatesTransformer forward. mma.sync bf16 split GEMMs.
// R10 = R9 resubmit (infra flake): R5 core + M64 GEMM for QKV/Wo/W2 +
// batched cvt (ncu launch #6 = QKV GEMM).
// ---------------------------------------------------------------------------

#define NLAYERS 8
#define BSZ     4
#define SEQ     512
#define DIM     512
#define NHEAD   16
#define KHD     32
#define FFD     2048
#define NDB     14
#define NROWS   (BSZ*SEQ)      // 2048
#define QKVN    (3*DIM)        // 1536

#define ATT_SCALE 0.17677669529663687f   // 1/sqrt(32)

// ------------------------- scratch (device globals) ------------------------
__device__ float g_h  [NROWS*DIM];
__device__ float g_h2 [NROWS*DIM];
__device__ float g_qkv[NROWS*QKVN];
__device__ float g_o  [NROWS*DIM];
__device__ unsigned char g_didx[BSZ*SEQ*SEQ];
__device__ float g_ekr [BSZ*SEQ*SEQ];

// split activations
__device__ __nv_bfloat16 g_xhi[NROWS*DIM];
__device__ __nv_bfloat16 g_xlo[NROWS*DIM];
__device__ __nv_bfloat16 g_fhi[NROWS*FFD];
__device__ __nv_bfloat16 g_flo[NROWS*FFD];

// split weights (pre-transposed, K-major)
__device__ __nv_bfloat16 g_wqkv_hi[NLAYERS*QKVN*DIM];
__device__ __nv_bfloat16 g_wqkv_lo[NLAYERS*QKVN*DIM];
__device__ __nv_bfloat16 g_wo_hi[NLAYERS*DIM*DIM];
__device__ __nv_bfloat16 g_wo_lo[NLAYERS*DIM*DIM];
__device__ __nv_bfloat16 g_w1_hi[NLAYERS*FFD*DIM];
__device__ __nv_bfloat16 g_w1_lo[NLAYERS*FFD*DIM];
__device__ __nv_bfloat16 g_w2_hi[NLAYERS*DIM*FFD];
__device__ __nv_bfloat16 g_w2_lo[NLAYERS*DIM*FFD];
__device__ float g_bqkv[NLAYERS*QKVN];

// ------------------------- PTX helpers --------------------------------------

__device__ __forceinline__ uint32_t smem_u32(const void* p) {
    uint32_t a;
    asm("{ .reg .u64 t; cvta.to.shared.u64 t, %1; cvt.u32.u64 %0, t; }" : "=r"(a) : "l"(p));
    return a;
}
#define SW128(off) ((off) ^ (((off) >> 3) & 0x70))

#define CP_ASYNC16(sm, gp) \
    asm volatile("cp.async.cg.shared.global [%0], [%1], 16;" :: "r"(sm), "l"(gp) : "memory")
#define CP_COMMIT() asm volatile("cp.async.commit_group;" ::: "memory")

#define LDSM4(r0, r1, r2, r3, addr) \
    asm volatile("ldmatrix.sync.aligned.m8n8.x4.shared.b16 {%0,%1,%2,%3}, [%4];" \
        : "=r"(r0), "=r"(r1), "=r"(r2), "=r"(r3) : "r"(addr))

#define MMA16816(c, a, b0, b1) \
    asm volatile("mma.sync.aligned.m16n8k16.row.col.f32.bf16.bf16.f32 " \
        "{%0,%1,%2,%3}, {%4,%5,%6,%7}, {%8,%9}, {%0,%1,%2,%3};" \
        : "+f"((c)[0]), "+f"((c)[1]), "+f"((c)[2]), "+f"((c)[3]) \
        : "r"((a)[0]), "r"((a)[1]), "r"((a)[2]), "r"((a)[3]), "r"(b0), "r"(b1))

__device__ __forceinline__ void split_bf16(float v, __nv_bfloat16& h, __nv_bfloat16& l) {
    h = __float2bfloat16(v);
    l = __float2bfloat16(v - __bfloat162float(h));
}

// ------------------------- precompute kernels ------------------------------

__global__ __launch_bounds__(256) void init_h_kernel(
    const int* __restrict__ cell_types, const float* __restrict__ cell_emb)
{
    int i = blockIdx.x * 256 + threadIdx.x;
    int row = i >> 9, d = i & 511;
    float v = cell_emb[cell_types[row] * DIM + d];
    g_h[i] = v;
    split_bf16(v, g_xhi[i], g_xlo[i]);
}

__global__ __launch_bounds__(256) void prep_kernel(
    const float* __restrict__ dist, const float* __restrict__ Kkr)
{
    __shared__ float ksum[NDB];
    if (threadIdx.x < NDB) {
        float s = 0.f;
        #pragma unroll
        for (int kk = 0; kk < KHD; kk++) s += Kkr[threadIdx.x * KHD + kk];
        ksum[threadIdx.x] = s;
    }
    __syncthreads();
    int i = blockIdx.x * 256 + threadIdx.x;
    float dv = dist[i];
    int idx = 0;
    #pragma unroll
    for (int j = 1; j <= NDB; j++) idx += (dv > 10.0f * (float)j);
    if (idx > NDB - 1) idx = NDB - 1;
    g_didx[i] = (unsigned char)idx;
    g_ekr[i]  = ksum[idx];
}

__global__ __launch_bounds__(256) void pack_bqkv_kernel(
    const float* __restrict__ bq, const float* __restrict__ bk,
    const float* __restrict__ bv)
{
    int i = blockIdx.x * 256 + threadIdx.x;
    int li = i / QKVN, j = i % QKVN;
    float v;
    if (j < DIM)            v = bq[li * DIM + j];
    else if (j < 2 * DIM)   v = bk[li * DIM + j - DIM];
    else                    v = bv[li * DIM + j - 2 * DIM];
    g_bqkv[i] = v;
}

// shared transpose+split body: W[K,N] row-major -> dst [N,K] K-major
__device__ __forceinline__ void cvt_tile(
    const float* __restrict__ src, __nv_bfloat16* __restrict__ hid,
    __nv_bfloat16* __restrict__ lod, int K, int N, int k0, int n0)
{
    __shared__ float t[32][33];
    int tx = threadIdx.x & 31, ty = threadIdx.x >> 5;
    #pragma unroll
    for (int r = 0; r < 4; r++)
        t[ty + 8 * r][tx] = src[(size_t)(k0 + ty + 8 * r) * N + n0 + tx];
    __syncthreads();
    #pragma unroll
    for (int r = 0; r < 4; r++) {
        int n = n0 + ty + 8 * r, k = k0 + tx;
        float v = t[tx][ty + 8 * r];
        __nv_bfloat16 h, l;
        split_bf16(v, h, l);
        hid[(size_t)n * K + k] = h;
        lod[(size_t)n * K + k] = l;
    }
}

// all 512x512 weights: z -> which (Wq/Wk/Wv/Wo), layer.  grid (16,16,32)
__global__ __launch_bounds__(256) void cvt_w512_kernel(
    const float* __restrict__ Wq, const float* __restrict__ Wk,
    const float* __restrict__ Wv, const float* __restrict__ Wo)
{
    int z = blockIdx.z, which = z >> 3, li = z & 7;
    size_t so = (size_t)li * DIM * DIM;
    const float* src;
    __nv_bfloat16 *hid, *lod;
    if (which == 0) { src = Wq + so; hid = g_wqkv_hi + (size_t)li*QKVN*DIM;             lod = g_wqkv_lo + (size_t)li*QKVN*DIM; }
    else if (which == 1) { src = Wk + so; hid = g_wqkv_hi + (size_t)li*QKVN*DIM + DIM*DIM;   lod = g_wqkv_lo + (size_t)li*QKVN*DIM + DIM*DIM; }
    else if (which == 2) { src = Wv + so; hid = g_wqkv_hi + (size_t)li*QKVN*DIM + 2*DIM*DIM; lod = g_wqkv_lo + (size_t)li*QKVN*DIM + 2*DIM*DIM; }
    else { src = Wo + so; hid = g_wo_hi + so; lod = g_wo_lo + so; }
    cvt_tile(src, hid, lod, DIM, DIM, blockIdx.y * 32, blockIdx.x * 32);
}

// W1 (z<8) and W2 (z>=8).  grid (64,16,16)
__global__ __launch_bounds__(256) void cvt_wff_kernel(
    const float* __restrict__ W1, const float* __restrict__ W2)
{
    int z = blockIdx.z, li = z & 7;
    if (z < 8) {
        cvt_tile(W1 + (size_t)li * DIM * FFD,
                 g_w1_hi + (size_t)li * FFD * DIM, g_w1_lo + (size_t)li * FFD * DIM,
                 DIM, FFD, blockIdx.y * 32, blockIdx.x * 32);
    } else {
        cvt_tile(W2 + (size_t)li * DIM * FFD,
                 g_w2_hi + (size_t)li * DIM * FFD, g_w2_lo + (size_t)li * DIM * FFD,
                 FFD, DIM, blockIdx.x * 32, blockIdx.y * 32);
    }
}

// ------------------------- M128 GEMM (R5 exact) ------------------------------
// CTA 128x64, 256 thr (4x2 warps, 32x32 warp tiles), 2-stage, occ 2.
// mode 0: fp32 out.  mode 2: exact-GELU + split bf16 out.

#define GSM_BUF   49152
#define GSM_TOTAL (2*GSM_BUF)

__device__ __forceinline__ void load_chunk(
    uint32_t base, int tid,
    const __nv_bfloat16* Ahi, const __nv_bfloat16* Alo,
    const __nv_bfloat16* Bhi, const __nv_bfloat16* Blo,
    int rowBase, int colBase, int K, int k0)
{
    #pragma unroll
    for (int t = 0; t < 4; t++) {
        int idx = tid + (t << 8);
        int r = idx >> 3, seg = idx & 7;
        uint32_t so = SW128((uint32_t)(r * 128 + seg * 16));
        size_t goff = (size_t)(rowBase + r) * K + k0 + seg * 8;
        CP_ASYNC16(base + so,         Ahi + goff);
        CP_ASYNC16(base + 16384 + so, Alo + goff);
    }
    #pragma unroll
    for (int t = 0; t < 2; t++) {
        int idx = tid + (t << 8);
        int r = idx >> 3, seg = idx & 7;
        uint32_t so = SW128((uint32_t)(r * 128 + seg * 16));
        size_t goff = (size_t)(colBase + r) * K + k0 + seg * 8;
        CP_ASYNC16(base + 32768 + so, Bhi + goff);
        CP_ASYNC16(base + 40960 + so, Blo + goff);
    }
}

__global__ __launch_bounds__(256, 2) void gemm_mma_kernel(
    const __nv_bfloat16* __restrict__ Ahi, const __nv_bfloat16* __restrict__ Alo,
    const __nv_bfloat16* __restrict__ Bhi, const __nv_bfloat16* __restrict__ Blo,
    const float* __restrict__ bias, float* __restrict__ C,
    __nv_bfloat16* __restrict__ Chi, __nv_bfloat16* __restrict__ Clo,
    int N, int K, int mode)
{
    extern __shared__ char smem[];
    uint32_t sb = smem_u32(smem);
    int tid = threadIdx.x, wid = tid >> 5, lane = tid & 31;
    int wr = wid >> 1, wc = wid & 1;
    int rowBase = blockIdx.y * 128, colBase = blockIdx.x * 64;
    int S = K >> 6;
    int rA = lane & 15, hs = lane >> 4;

    float acc[2][4][4];
    #pragma unroll
    for (int mt = 0; mt < 2; mt++)
        #pragma unroll
        for (int nt = 0; nt < 4; nt++)
            #pragma unroll
            for (int e = 0; e < 4; e++) acc[mt][nt][e] = 0.f;

    load_chunk(sb, tid, Ahi, Alo, Bhi, Blo, rowBase, colBase, K, 0);
    CP_COMMIT();

    for (int i = 0; i < S; i++) {
        if (i + 1 < S) {
            load_chunk(sb + ((i + 1) & 1) * GSM_BUF, tid,
                       Ahi, Alo, Bhi, Blo, rowBase, colBase, K, (i + 1) << 6);
            CP_COMMIT();
            asm volatile("cp.async.wait_group 1;" ::: "memory");
        } else {
            asm volatile("cp.async.wait_group 0;" ::: "memory");
        }
        __syncthreads();

        uint32_t aBh = sb + (i & 1) * GSM_BUF;
        uint32_t aBl = aBh + 16384;
        uint32_t bBh = aBh + 32768;
        uint32_t bBl = aBh + 40960;

        #pragma unroll
        for (int ks = 0; ks < 4; ks++) {
            int segoff = (ks * 2 + hs) * 16;
            uint32_t ah[2][4], al[2][4], bh[2][4], bl[2][4];
            #pragma unroll
            for (int mt = 0; mt < 2; mt++) {
                int row = wr * 32 + mt * 16 + rA;
                uint32_t off = SW128((uint32_t)(row * 128 + segoff));
                LDSM4(ah[mt][0], ah[mt][1], ah[mt][2], ah[mt][3], aBh + off);
                LDSM4(al[mt][0], al[mt][1], al[mt][2], al[mt][3], aBl + off);
            }
            #pragma unroll
            for (int g = 0; g < 2; g++) {
                int row = wc * 32 + g * 16 + rA;
                uint32_t off = SW128((uint32_t)(row * 128 + segoff));
                LDSM4(bh[g][0], bh[g][1], bh[g][2], bh[g][3], bBh + off);
                LDSM4(bl[g][0], bl[g][1], bl[g][2], bl[g][3], bBl + off);
            }
            #pragma unroll
            for (int mt = 0; mt < 2; mt++)
                #pragma unroll
                for (int nt = 0; nt < 4; nt++) {
                    int g = nt >> 1, s = nt & 1;
                    MMA16816(acc[mt][nt], ah[mt], bh[g][s], bh[g][s + 2]);
                    MMA16816(acc[mt][nt], ah[mt], bl[g][s], bl[g][s + 2]);
                    MMA16816(acc[mt][nt], al[mt], bh[g][s], bh[g][s + 2]);
                }
        }
        __syncthreads();
    }

    int tg = lane >> 2, tq = lane & 3;
    #pragma unroll
    for (int mt = 0; mt < 2; mt++) {
        #pragma unroll
        for (int nt = 0; nt < 4; nt++) {
            int c0 = colBase + wc * 32 + nt * 8 + tq * 2;
            float b0 = bias[c0], b1 = bias[c0 + 1];
            int r0 = rowBase + wr * 32 + mt * 16 + tg;
            float v00 = acc[mt][nt][0] + b0, v01 = acc[mt][nt][1] + b1;
            float v10 = acc[mt][nt][2] + b0, v11 = acc[mt][nt][3] + b1;
            if (mode == 2) {
                v00 = 0.5f * v00 * (1.0f + erff(v00 * 0.70710678118654752f));
                v01 = 0.5f * v01 * (1.0f + erff(v01 * 0.70710678118654752f));
                v10 = 0.5f * v10 * (1.0f + erff(v10 * 0.70710678118654752f));
                v11 = 0.5f * v11 * (1.0f + erff(v11 * 0.70710678118654752f));
                __nv_bfloat162 h0, l0, h1, l1;
                split_bf16(v00, h0.x, l0.x); split_bf16(v01, h0.y, l0.y);
                split_bf16(v10, h1.x, l1.x); split_bf16(v11, h1.y, l1.y);
                *(__nv_bfloat162*)&Chi[(size_t)r0 * N + c0]       = h0;
                *(__nv_bfloat162*)&Clo[(size_t)r0 * N + c0]       = l0;
                *(__nv_bfloat162*)&Chi[(size_t)(r0 + 8) * N + c0] = h1;
                *(__nv_bfloat162*)&Clo[(size_t)(r0 + 8) * N + c0] = l1;
            } else {
                *(float2*)&C[(size_t)r0 * N + c0]       = make_float2(v00, v01);
                *(float2*)&C[(size_t)(r0 + 8) * N + c0] = make_float2(v10, v11);
            }
        }
    }
}

// ------------------------- M64 GEMM -----------------------------------------
// CTA 64x64, 256 thr (2x4 warps, 32x16 warp tiles), 2-stage, occ 3.
// fp32 + bias out only.

#define GSM64_BUF   32768
#define GSM64_TOTAL (2*GSM64_BUF)

__device__ __forceinline__ void load_chunk64(
    uint32_t base, int tid,
    const __nv_bfloat16* Ahi, const __nv_bfloat16* Alo,
    const __nv_bfloat16* Bhi, const __nv_bfloat16* Blo,
    int rowBase, int colBase, int K, int k0)
{
    #pragma unroll
    for (int t = 0; t < 2; t++) {
        int idx = tid + (t << 8);                 // 0..511 : 64 rows x 8 segs
        int r = idx >> 3, seg = idx & 7;
        uint32_t so = SW128((uint32_t)(r * 128 + seg * 16));
        size_t ga = (size_t)(rowBase + r) * K + k0 + seg * 8;
        size_t gb = (size_t)(colBase + r) * K + k0 + seg * 8;
        CP_ASYNC16(base + so,         Ahi + ga);
        CP_ASYNC16(base + 8192 + so,  Alo + ga);
        CP_ASYNC16(base + 16384 + so, Bhi + gb);
        CP_ASYNC16(base + 24576 + so, Blo + gb);
    }
}

__global__ __launch_bounds__(256, 3) void gemm_mma64_kernel(
    const __nv_bfloat16* __restrict__ Ahi, const __nv_bfloat16* __restrict__ Alo,
    const __nv_bfloat16* __restrict__ Bhi, const __nv_bfloat16* __restrict__ Blo,
    const float* __restrict__ bias, float* __restrict__ C,
    int N, int K)
{
    extern __shared__ char smem[];
    uint32_t sb = smem_u32(smem);
    int tid = threadIdx.x, wid = tid >> 5, lane = tid & 31;
    int wr = wid >> 2, wc = wid & 3;               // 2 x 4 warps
    int rowBase = blockIdx.y * 64, colBase = blockIdx.x * 64;
    int S = K >> 6;
    int rA = lane & 15, hs = lane >> 4;

    float acc[2][2][4];
    #pragma unroll
    for (int mt = 0; mt < 2; mt++)
        #pragma unroll
        for (int s = 0; s < 2; s++)
            #pragma unroll
            for (int e = 0; e < 4; e++) acc[mt][s][e] = 0.f;

    load_chunk64(sb, tid, Ahi, Alo, Bhi, Blo, rowBase, colBase, K, 0);
    CP_COMMIT();

    for (int i = 0; i < S; i++) {
        if (i + 1 < S) {
            load_chunk64(sb + ((i + 1) & 1) * GSM64_BUF, tid,
                         Ahi, Alo, Bhi, Blo, rowBase, colBase, K, (i + 1) << 6);
            CP_COMMIT();
            asm volatile("cp.async.wait_group 1;" ::: "memory");
        } else {
            asm volatile("cp.async.wait_group 0;" ::: "memory");
        }
        __syncthreads();

        uint32_t base = sb + (i & 1) * GSM64_BUF;
        #pragma unroll
        for (int ks = 0; ks < 4; ks++) {
            int segoff = (ks * 2 + hs) * 16;
            uint32_t ah[2][4], al[2][4], bh[4], bl[4];
            #pragma unroll
            for (int mt = 0; mt < 2; mt++) {
                int row = wr * 32 + mt * 16 + rA;
                uint32_t off = SW128((uint32_t)(row * 128 + segoff));
                LDSM4(ah[mt][0], ah[mt][1], ah[mt][2], ah[mt][3], base + off);
                LDSM4(al[mt][0], al[mt][1], al[mt][2], al[mt][3], base + 8192 + off);
            }
            {
                int row = wc * 16 + rA;
                uint32_t off = SW128((uint32_t)(row * 128 + segoff));
                LDSM4(bh[0], bh[1], bh[2], bh[3], base + 16384 + off);
                LDSM4(bl[0], bl[1], bl[2], bl[3], base + 24576 + off);
            }
            #pragma unroll
            for (int mt = 0; mt < 2; mt++)
                #pragma unroll
                for (int s = 0; s < 2; s++) {
                    MMA16816(acc[mt][s], ah[mt], bh[s], bh[s + 2]);
                    MMA16816(acc[mt][s], ah[mt], bl[s], bl[s + 2]);
                    MMA16816(acc[mt][s], al[mt], bh[s], bh[s + 2]);
                }
        }
        __syncthreads();
    }

    int tg = lane >> 2, tq = lane & 3;
    #pragma unroll
    for (int mt = 0; mt < 2; mt++) {
        #pragma unroll
        for (int s = 0; s < 2; s++) {
            int c0 = colBase + wc * 16 + s * 8 + tq * 2;
            float b0 = bias[c0], b1 = bias[c0 + 1];
            int r0 = rowBase + wr * 32 + mt * 16 + tg;
            *(float2*)&C[(size_t)r0 * N + c0] =
                make_float2(acc[mt][s][0] + b0, acc[mt][s][1] + b1);
            *(float2*)&C[(size_t)(r0 + 8) * N + c0] =
                make_float2(acc[mt][s][2] + b0, acc[mt][s][3] + b1);
        }
    }
}

// ------------------------- attention (R5 exact) ------------------------------

#define ATT_SMEM_FLOATS (32*512 + 512*32 + 14*512 + 8*512 + 448*3 + 8*16)

__global__ __launch_bounds__(256) void attn_kernel(
    const float* __restrict__ Kqk, const float* __restrict__ Kqr,
    const float* __restrict__ Vqk, const float* __restrict__ Vqr,
    const float* __restrict__ Vkr)
{
    extern __shared__ float sm[];
    float* Kt    = sm;
    float* Vs    = Kt + 32 * 512;
    float* kEt   = Vs + 512 * 32;
    float* ps    = kEt + 14 * 512;
    float* tKqkT = ps + 8 * 512;
    float* tKqr  = tKqkT + 448;
    float* tVs   = tKqr + 448;
    float* wb    = tVs + 448;

    int bh = blockIdx.x;
    int b = bh >> 4, h = bh & 15;
    int tid = threadIdx.x, lane = tid & 31, warp = tid >> 5;

    const float* qb = g_qkv + ((size_t)b * SEQ) * QKVN + h * KHD;
    const float* kb = qb + DIM;
    const float* vb = qb + 2 * DIM;

    for (int i = tid; i < NDB * KHD; i += 256) {
        int d = i / KHD, kk = i % KHD;
        tKqkT[kk * NDB + d] = Kqk[i];
        tKqr[i] = Kqr[i];
        tVs[i]  = Vqk[i] + Vqr[i] + Vkr[i];
    }
    for (int i = tid; i < SEQ * 8; i += 256) {
        int x = i >> 3, g = (i & 7) << 2;
        float4 k4 = *(const float4*)&kb[(size_t)x * QKVN + g];
        Kt[(g + 0) * SEQ + x] = k4.x; Kt[(g + 1) * SEQ + x] = k4.y;
        Kt[(g + 2) * SEQ + x] = k4.z; Kt[(g + 3) * SEQ + x] = k4.w;
        float4 v4 = *(const float4*)&vb[(size_t)x * QKVN + g];
        *(float4*)&Vs[x * KHD + g] = v4;
    }
    __syncthreads();

    for (int i = tid; i < NDB * SEQ; i += 256) {
        int d = i >> 9, x = i & 511;
        float s = 0.f;
        #pragma unroll
        for (int kk = 0; kk < KHD; kk++)
            s = fmaf(Kt[kk * SEQ + x], tKqr[d * KHD + kk], s);
        kEt[i] = s;
    }
    __syncthreads();

    int l0 = blockIdx.y * 64 + warp * 8;
    for (int r = 0; r < 8; r++) {
        int l = l0 + r;
        float qreg = qb[(size_t)l * QKVN + lane];
        float e[16];
        #pragma unroll
        for (int j = 0; j < 16; j++) e[j] = 0.f;
        float qE = 0.f;
        #pragma unroll
        for (int kk = 0; kk < KHD; kk++) {
            float qk = __shfl_sync(0xffffffffu, qreg, kk);
            #pragma unroll
            for (int j = 0; j < 16; j++)
                e[j] = fmaf(qk, Kt[kk * SEQ + lane + j * 32], e[j]);
            if (lane < NDB) qE = fmaf(qk, tKqkT[kk * NDB + lane], qE);
        }

        const unsigned char* drow = &g_didx[((size_t)b * SEQ + l) * SEQ];
        const float*         erow = &g_ekr [((size_t)b * SEQ + l) * SEQ];
        int dly[16];
        float m = -1e30f;
        #pragma unroll
        for (int j = 0; j < 16; j++) {
            int x = lane + j * 32;
            int d = drow[x];
            dly[j] = d;
            float biasv = __shfl_sync(0xffffffffu, qE, d) + kEt[d * SEQ + x] + erow[x];
            e[j] = (e[j] + biasv) * ATT_SCALE;
            m = fmaxf(m, e[j]);
        }
        #pragma unroll
        for (int off = 16; off; off >>= 1)
            m = fmaxf(m, __shfl_xor_sync(0xffffffffu, m, off));

        if (lane < 16) wb[warp * 16 + lane] = 0.f;
        __syncwarp();

        float sum = 0.f;
        float pj[16];
        #pragma unroll
        for (int j = 0; j < 16; j++) {
            float p = expf(e[j] - m);
            pj[j] = p;
            sum += p;
            ps[warp * SEQ + lane + j * 32] = p;
        }
        #pragma unroll
        for (int off = 16; off; off >>= 1)
            sum += __shfl_xor_sync(0xffffffffu, sum, off);
        #pragma unroll
        for (int j = 0; j < 16; j++)
            atomicAdd(&wb[warp * 16 + dly[j]], pj[j]);
        __syncwarp();

        float acc = 0.f;
        const float* pw = &ps[warp * SEQ];
        for (int x = 0; x < SEQ; x += 4) {
            float4 p4 = *(const float4*)&pw[x];
            acc = fmaf(p4.x, Vs[(x + 0) * KHD + lane], acc);
            acc = fmaf(p4.y, Vs[(x + 1) * KHD + lane], acc);
            acc = fmaf(p4.z, Vs[(x + 2) * KHD + lane], acc);
            acc = fmaf(p4.w, Vs[(x + 3) * KHD + lane], acc);
        }
        #pragma unroll
        for (int d = 0; d < NDB; d++)
            acc = fmaf(wb[warp * 16 + d], tVs[d * KHD + lane], acc);

        float z = acc / sum;
        size_t oidx = ((size_t)b * SEQ + l) * DIM + h * KHD + lane;
        split_bf16(z, g_xhi[oidx], g_xlo[oidx]);
    }
}

// ------------------------- residual + layernorm (R5 exact) -------------------

__global__ __launch_bounds__(256) void add_ln_kernel(
    const float* __restrict__ x, const float* __restrict__ y,
    const float* __restrict__ g, const float* __restrict__ b,
    float* __restrict__ out)
{
    __shared__ float red[256];
    int row = blockIdx.x, t = threadIdx.x;
    const float* xr = x + (size_t)row * DIM;
    const float* yr = y + (size_t)row * DIM;
    float v0 = xr[t] + yr[t];
    float v1 = xr[t + 256] + yr[t + 256];
    red[t] = v0 + v1;
    __syncthreads();
    for (int s = 128; s; s >>= 1) { if (t < s) red[t] += red[t + s]; __syncthreads(); }
    float mu = red[0] * (1.0f / 512.0f);
    __syncthreads();
    float d0 = v0 - mu, d1 = v1 - mu;
    red[t] = d0 * d0 + d1 * d1;
    __syncthreads();
    for (int s = 128; s; s >>= 1) { if (t < s) red[t] += red[t + s]; __syncthreads(); }
    float rs = rsqrtf(red[0] * (1.0f / 512.0f) + 1e-5f);
    float o0 = d0 * rs * g[t] + b[t];
    float o1 = d1 * rs * g[t + 256] + b[t + 256];
    size_t i0 = (size_t)row * DIM + t;
    out[i0] = o0; out[i0 + 256] = o1;
    split_bf16(o0, g_xhi[i0], g_xlo[i0]);
    split_bf16(o1, g_xhi[i0 + 256], g_xlo[i0 + 256]);
}

// ------------------------- pooling + MLP head ------------------------------

__global__ __launch_bounds__(256) void head_kernel(
    const float* __restrict__ Wm1, const float* __restrict__ bm1,
    const float* __restrict__ Wm2, const float* __restrict__ bm2,
    float* __restrict__ out)
{
    __shared__ float pooled[DIM];
    __shared__ float hidden[DIM];
    __shared__ float red[256];
    int b = blockIdx.x, t = threadIdx.x;
    const float* hb = g_h + (size_t)b * SEQ * DIM;
    for (int d = t; d < DIM; d += 256) {
        float s = 0.f;
        for (int l = 0; l < SEQ; l++) s += hb[(size_t)l * DIM + d];
        pooled[d] = s;
    }
    __syncthreads();
    for (int m = t; m < DIM; m += 256) {
        float s = bm1[m];
        for (int kd = 0; kd < DIM; kd++)
            s = fmaf(pooled[kd], Wm1[(size_t)kd * DIM + m], s);
        hidden[m] = fmaxf(s, 0.f);
    }
    __syncthreads();
    red[t] = hidden[t] * Wm2[t] + hidden[t + 256] * Wm2[t + 256];
    __syncthreads();
    for (int s = 128; s; s >>= 1) { if (t < s) red[t] += red[t + s]; __syncthreads(); }
    if (t == 0) out[b] = red[0] + bm2[0];
}

// ------------------------- launcher ----------------------------------------

extern "C" void kernel_launch(void* const* d_in, const int* in_sizes, int n_in,
                              void* d_out, int out_size)
{
    (void)n_in; (void)out_size;

    const int*   cell_types = (const int*)  d_in[0];
    const float* dist       = (const float*)d_in[1];
    const float* cell_emb   = (const float*)d_in[2];
    const float* Kqk = (const float*)d_in[3];
    const float* Kqr = (const float*)d_in[4];
    const float* Kkr = (const float*)d_in[5];
    const float* Vqk = (const float*)d_in[6];
    const float* Vqr = (const float*)d_in[7];
    const float* Vkr = (const float*)d_in[8];

    const float *Wq, *bq, *Wk, *bk, *Wv, *bv, *Wo, *bo;
    if (in_sizes[10] == NLAYERS * DIM) {
        Wq = (const float*)d_in[9];  bq = (const float*)d_in[10];
        Wk = (const float*)d_in[11]; bk = (const float*)d_in[12];
        Wv = (const float*)d_in[13]; bv = (const float*)d_in[14];
        Wo = (const float*)d_in[15]; bo = (const float*)d_in[16];
    } else {
        Wq = (const float*)d_in[9];  Wk = (const float*)d_in[10];
        Wv = (const float*)d_in[11]; Wo = (const float*)d_in[12];
        bq = (const float*)d_in[13]; bk = (const float*)d_in[14];
        bv = (const float*)d_in[15]; bo = (const float*)d_in[16];
    }
    const float* W1  = (const float*)d_in[17];
    const float* b1  = (const float*)d_in[18];
    const float* W2  = (const float*)d_in[19];
    const float* b2  = (const float*)d_in[20];
    const float* gm1 = (const float*)d_in[21];
    const float* be1 = (const float*)d_in[22];
    const float* gm2 = (const float*)d_in[23];
    const float* be2 = (const float*)d_in[24];
    const float* Wm1 = (const float*)d_in[25];
    const float* bm1 = (const float*)d_in[26];
    const float* Wm2 = (const float*)d_in[27];
    const float* bm2 = (const float*)d_in[28];

    static float *h = nullptr, *h2, *qkv, *ob, *bqkv;
    static __nv_bfloat16 *xhi, *xlo, *fhi, *flo;
    static __nv_bfloat16 *wqkvh, *wqkvl, *woh, *wol, *w1h, *w1l, *w2h, *w2l;
    if (!h) {
        cudaGetSymbolAddress((void**)&h,    g_h);
        cudaGetSymbolAddress((void**)&h2,   g_h2);
        cudaGetSymbolAddress((void**)&qkv,  g_qkv);
        cudaGetSymbolAddress((void**)&ob,   g_o);
        cudaGetSymbolAddress((void**)&bqkv, g_bqkv);
        cudaGetSymbolAddress((void**)&xhi,  g_xhi);
        cudaGetSymbolAddress((void**)&xlo,  g_xlo);
        cudaGetSymbolAddress((void**)&fhi,  g_fhi);
        cudaGetSymbolAddress((void**)&flo,  g_flo);
        cudaGetSymbolAddress((void**)&wqkvh, g_wqkv_hi);
        cudaGetSymbolAddress((void**)&wqkvl, g_wqkv_lo);
        cudaGetSymbolAddress((void**)&woh,  g_wo_hi);
        cudaGetSymbolAddress((void**)&wol,  g_wo_lo);
        cudaGetSymbolAddress((void**)&w1h,  g_w1_hi);
        cudaGetSymbolAddress((void**)&w1l,  g_w1_lo);
        cudaGetSymbolAddress((void**)&w2h,  g_w2_hi);
        cudaGetSymbolAddress((void**)&w2l,  g_w2_lo);
        cudaFuncSetAttribute(attn_kernel,
            cudaFuncAttributeMaxDynamicSharedMemorySize,
            ATT_SMEM_FLOATS * (int)sizeof(float));
        cudaFuncSetAttribute(gemm_mma_kernel,
            cudaFuncAttributeMaxDynamicSharedMemorySize, GSM_TOTAL);
        cudaFuncSetAttribute(gemm_mma64_kernel,
            cudaFuncAttributeMaxDynamicSharedMemorySize, GSM64_TOTAL);
    }
    const int attSmem = ATT_SMEM_FLOATS * (int)sizeof(float);

    // launch order fixed so that launch #6 (ncu -s 5 -c 1) = first QKV GEMM
    init_h_kernel<<<NROWS * DIM / 256, 256>>>(cell_types, cell_emb);     // 1
    prep_kernel<<<BSZ * SEQ * SEQ / 256, 256>>>(dist, Kkr);              // 2
    pack_bqkv_kernel<<<NLAYERS * QKVN / 256, 256>>>(bq, bk, bv);         // 3
    cvt_w512_kernel<<<dim3(16, 16, 32), 256>>>(Wq, Wk, Wv, Wo);          // 4
    cvt_wff_kernel<<<dim3(64, 16, 16), 256>>>(W1, W2);                   // 5

    dim3 gQKV(QKVN / 64, NROWS / 64);   // (24,32) = 768 CTAs
    dim3 gD64(DIM / 64, NROWS / 64);    // (8,32)  = 256 CTAs
    dim3 gF(FFD / 64, NROWS / 128);     // (32,16) = 512 CTAs (M128)
    dim3 gAtt(BSZ * NHEAD, SEQ / 64);

    for (int li = 0; li < NLAYERS; li++) {
        const __nv_bfloat16* lwqh = wqkvh + (size_t)li * QKVN * DIM;
        const __nv_bfloat16* lwql = wqkvl + (size_t)li * QKVN * DIM;
        const __nv_bfloat16* lwoh = woh + (size_t)li * DIM * DIM;
        const __nv_bfloat16* lwol = wol + (size_t)li * DIM * DIM;
        const __nv_bfloat16* lw1h = w1h + (size_t)li * FFD * DIM;
        const __nv_bfloat16* lw1l = w1l + (size_t)li * FFD * DIM;
        const __nv_bfloat16* lw2h = w2h + (size_t)li * DIM * FFD;
        const __nv_bfloat16* lw2l = w2l + (size_t)li * DIM * FFD;

        gemm_mma64_kernel<<<gQKV, 256, GSM64_TOTAL>>>(xhi, xlo, lwqh, lwql,
            bqkv + (size_t)li * QKVN, qkv, QKVN, DIM);                   // 6 (layer 0)

        attn_kernel<<<gAtt, 256, attSmem>>>(Kqk, Kqr, Vqk, Vqr, Vkr);

        gemm_mma64_kernel<<<gD64, 256, GSM64_TOTAL>>>(xhi, xlo, lwoh, lwol,
            bo + li * DIM, ob, DIM, DIM);
        add_ln_kernel<<<NROWS, 256>>>(h, ob, gm1 + li * DIM, be1 + li * DIM, h2);

        gemm_mma_kernel<<<gF, 256, GSM_TOTAL>>>(xhi, xlo, lw1h, lw1l,
            b1 + li * FFD, nullptr, fhi, flo, FFD, DIM, 2);

        gemm_mma64_kernel<<<gD64, 256, GSM64_TOTAL>>>(fhi, flo, lw2h, lw2l,
            b2 + li * DIM, ob, DIM, FFD);
        add_ln_kernel<<<NROWS, 256>>>(h2, ob, gm2 + li * DIM, be2 + li * DIM, h);
    }

    head_kernel<<<BSZ, 256>>>(Wm1, bm1, Wm2, bm2, (float*)d_out);
}